// round 11
// baseline (speedup 1.0000x reference)
#include <cuda_runtime.h>

#define Bn   8
#define Tn   64
#define NIn  256
#define Nn   512
#define NOn  32
#define Dn   4
#define NBLK 128
#define NTHR 512
#define OB   32

// ---------------- global scratch (static __device__, allocation-free) --------
__device__ float          g_inp[Bn * Tn * Nn];     // input projection (b,t,n)
__device__ float          g_rout[Tn * Bn * Nn];    // rec_out  (t,b,n)
__device__ float          g_rsyn[Tn * Bn * Nn];    // spike*(1+w_p) recorded
__device__ float          g_rxb[Tn * Bn * Nn];     // rec x_bar
__device__ float2         g_pk[(size_t)Nn * Nn];   // per-(o,e): {wv, bf16x2(A_p,A_d)}
__device__ unsigned char  g_di[(size_t)Nn * Nn];   // per-(o,e): delay bin
__device__ float          g_h2[Bn * Tn * NOn];     // readout pre-scan
__device__ unsigned       g_barcnt;                // grid barrier counter

// ---------------- K0: reset barrier, zero rings, build packed matrix --------
__global__ void k_pack(const float* __restrict__ w,
                       const float* __restrict__ wsg,
                       const float* __restrict__ Ap,
                       const float* __restrict__ Ad,
                       const float* __restrict__ dmap) {
    if (blockIdx.x == 0 && threadIdx.x == 0) g_barcnt = 0u;

    // zero the three recording rings (needed for replay determinism and the
    // (t - delay) < 0 wrap reads)
    {
        const int per = Tn * Bn * Nn / 4;      // float4 count per array
        float4 z = make_float4(0.f, 0.f, 0.f, 0.f);
        for (int i = blockIdx.x * blockDim.x + threadIdx.x; i < 3 * per;
             i += gridDim.x * blockDim.x) {
            if (i < per)            ((float4*)g_rout)[i] = z;
            else if (i < 2 * per)   ((float4*)g_rsyn)[i - per] = z;
            else                    ((float4*)g_rxb)[i - 2 * per] = z;
        }
    }

    // 32x32 tile transpose: read (e,o)-major coalesced, write (o,e)-major coalesced
    __shared__ float         swv[32][33];
    __shared__ unsigned      sa[32][33];
    __shared__ unsigned char sdi[32][33];

    int tx = threadIdx.x & 31, ty = threadIdx.x >> 5;     // 32 x 8
    int te = (blockIdx.x & 15) << 5;
    int to = (blockIdx.x >> 4) << 5;

    for (int j = 0; j < 4; j++) {
        int e = te + ty + 8 * j, o = to + tx;
        size_t eo = (size_t)e * Nn + o;
        float wv = wsg[e] * fabsf(w[eo]);
        // round-to-nearest-even bf16 packing of A_p, A_d
        unsigned ua = __float_as_uint(Ap[eo]);
        unsigned ub = __float_as_uint(Ad[eo]);
        unsigned ap = (ua + 0x7FFFu + ((ua >> 16) & 1u)) >> 16;
        unsigned ad = (ub + 0x7FFFu + ((ub >> 16) & 1u)) >> 16;
        int d = 0;
        for (int dd = 0; dd < Dn; dd++)
            if (dmap[((size_t)dd * Nn + e) * Nn + o] > 0.5f) d = dd;
        swv[ty + 8 * j][tx] = wv;
        sa[ty + 8 * j][tx]  = ap | (ad << 16);
        sdi[ty + 8 * j][tx] = (unsigned char)d;
    }
    __syncthreads();
    for (int j = 0; j < 4; j++) {
        int o = to + ty + 8 * j, e = te + tx;
        g_pk[(size_t)o * Nn + e] =
            make_float2(swv[tx][ty + 8 * j], __uint_as_float(sa[tx][ty + 8 * j]));
        g_di[(size_t)o * Nn + e] = sdi[tx][ty + 8 * j];
    }
}

// ---------------- K_in: inp = einsum('btc,cn->btn', inputs, w_in) ------------
__global__ void k_inp(const float* __restrict__ x, const float* __restrict__ win) {
    __shared__ float xs[8][NIn];
    int bt0 = blockIdx.x * 8;                 // 64 blocks x 8 rows = 512 (b,t)
    int tid = threadIdx.x;                    // 256
    for (int i = tid; i < 8 * NIn; i += 256) {
        int r = i >> 8, c = i & 255;
        xs[r][c] = x[(size_t)(bt0 + r) * NIn + c];
    }
    __syncthreads();
    for (int half = 0; half < 2; half++) {
        int n = tid + half * 256;
        float acc[8] = {0.f, 0.f, 0.f, 0.f, 0.f, 0.f, 0.f, 0.f};
        for (int c = 0; c < NIn; c++) {
            float wv = win[(size_t)c * Nn + n];
#pragma unroll
            for (int r = 0; r < 8; r++) acc[r] = fmaf(xs[r][c], wv, acc[r]);
        }
#pragma unroll
        for (int r = 0; r < 8; r++) g_inp[(size_t)(bt0 + r) * Nn + n] = acc[r];
    }
}

// ---------------- K1: persistent stepping kernel -----------------------------
// CTA = (batch b, 32 output neurons). w_stdp slab + all state lives in smem.
__global__ void __launch_bounds__(NTHR)
k_step(const int* __restrict__ delays, const float* __restrict__ p) {
    extern __shared__ char smem[];
    float*  ws   = (float*)smem;                                   // [OB][Nn] 64KB
    float4* gbuf = (float4*)(smem + OB * Nn * 4);                  // [Dn][Nn] 32KB
    float*  aux  = (float*)(smem + OB * Nn * 4 + Dn * Nn * 16);
    float* mem_s = aux +   0;  float* wp_s  = aux +  32;
    float* xb_s  = aux +  64;  float* up_s  = aux +  96;
    float* ud_s  = aux + 128;  float* potg  = aux + 160;
    float* depg  = aux + 192;  float* syn_s = aux + 224;
    float* p_s   = aux + 256;  float* pd_s  = aux + 288;
    int*   dly   = (int*)(aux + 320);

    const int tid = threadIdx.x;
    const int cta = blockIdx.x;
    const int b   = cta >> 4;
    const int o0  = (cta & 15) << 5;
    const int lane = tid & 31, wrp = tid >> 5;

    for (int i = tid; i < OB * Nn; i += NTHR) ws[i] = 1.0f;
    if (tid < 32) {
        mem_s[tid] = 0.f; wp_s[tid] = 0.f; xb_s[tid] = 0.f;
        up_s[tid] = 0.f;  ud_s[tid] = 0.f;
        float pv = p[o0 + tid];
        p_s[tid] = pv; pd_s[tid] = (pv < 0.f) ? 1.f : 0.f;
    }
    if (tid < 4) dly[tid] = delays[tid];
    __syncthreads();
    const int d0 = dly[0], d1 = dly[1], d2 = dly[2], d3 = dly[3];

    volatile unsigned* vb = &g_barcnt;
    float memv = 0.f, spk = 0.f;             // live in tid<32 threads only

    for (int t = 0; t < Tn; t++) {
        // ---- Phase A: spikes, recordings, fast state (pre-update semantics) ----
        if (tid < 32) {
            memv = mem_s[tid];
            float wpv = wp_s[tid], xbv = xb_s[tid];
            float upv = up_s[tid], udv = ud_s[tid];
            spk = (memv - 1.0f > 0.f) ? 1.0f : 0.0f;
            size_t ro = ((size_t)t * Bn + b) * Nn + o0 + tid;
            g_rout[ro] = spk;
            g_rsyn[ro] = spk * (1.0f + wpv);
            g_rxb[ro]  = xbv;
            potg[tid] = spk * fmaxf(upv, 0.f);      // spike * relu(u_pot_pre)
            depg[tid] = fmaxf(udv, 0.f);            // relu(u_dep_pre)
            wp_s[tid] = 0.85f * wpv + spk * p_s[tid] * (1.0f + pd_s[tid] * wpv);
            xb_s[tid] = 0.95f * xbv + 0.05f * spk;
            up_s[tid] = 0.95f * upv + 0.05f * memv;
            ud_s[tid] = 0.95f * udv + 0.05f * memv;
        }
        // ---- grid barrier (CG-style: sync, fence, arrive, spin, fence, sync) ----
        __syncthreads();
        if (tid == 0) {
            __threadfence();
            atomicAdd(&g_barcnt, 1u);
            unsigned tgt = (unsigned)NBLK * (unsigned)(t + 1);
            while (*vb < tgt) __nanosleep(64);
            __threadfence();
        }
        __syncthreads();
        // ---- stage delayed recordings into conflict-free smem ----
        {
            int tds0 = (t - d0) & 63, tds1 = (t - d1) & 63;
            int tds2 = (t - d2) & 63, tds3 = (t - d3) & 63;
            int tds[4] = {tds0, tds1, tds2, tds3};
#pragma unroll
            for (int k = 0; k < (Dn * Nn) / NTHR; k++) {    // 4 iterations
                int idx = tid + k * NTHR;
                int dd = idx >> 9, e = idx & 511;
                size_t off = ((size_t)tds[dd] * Bn + b) * Nn + e;
                float a  = __ldcg(&g_rout[off]);
                float s  = __ldcg(&g_rsyn[off]);
                float xx = __ldcg(&g_rxb[off]);
                gbuf[idx] = make_float4(a, s, xx, 0.f);
            }
        }
        __syncthreads();
        // ---- Phase B: fused syn reduction + w_stdp update (each warp: 2 o's) ----
#pragma unroll
        for (int pass = 0; pass < 2; pass++) {
            int ol = wrp * 2 + pass;
            const float2* __restrict__ pko = g_pk + (size_t)(o0 + ol) * Nn;
            const unsigned char* __restrict__ dio = g_di + (size_t)(o0 + ol) * Nn;
            float* wso = ws + ol * Nn;
            float pot = potg[ol], dep = depg[ol];
            float acc = 0.f;
#pragma unroll
            for (int i = 0; i < 16; i++) {
                int e = lane + (i << 5);
                float2 m = __ldg(&pko[e]);
                int dd = (int)__ldg(&dio[e]);
                float4 g = gbuf[(dd << 9) + e];   // {out, synp, xb, -}
                float wsv = wso[e];
                unsigned u = __float_as_uint(m.y);
                float ap = __uint_as_float((u & 0xFFFFu) << 16);
                float ad = __uint_as_float(u & 0xFFFF0000u);
                acc = fmaf(g.y * m.x, wsv, acc);              // syn (pre-update ws)
                float dw = g.z * ap * pot - g.x * ad * dep;   // dW_pot - dW_dep
                wso[e] = fminf(fmaxf(wsv + dw, 0.f), 2.f);
            }
#pragma unroll
            for (int off = 16; off; off >>= 1)
                acc += __shfl_xor_sync(0xFFFFFFFFu, acc, off);
            if (lane == 0) syn_s[ol] = acc;
        }
        __syncthreads();
        // ---- Phase C: membrane integration ----
        if (tid < 32) {
            float inpv = g_inp[((size_t)b * Tn + t) * Nn + o0 + tid];
            mem_s[tid] = 0.9f * memv + inpv + syn_s[tid] - spk;
        }
    }
}

// ---------------- readout: h2 = rec_out @ w_out ------------------------------
__global__ void k_h2(const float* __restrict__ wout) {
    int bt = blockIdx.x;                 // 512 blocks: bt = b*Tn + t
    int b = bt >> 6, t = bt & 63;
    int oo = threadIdx.x;                // 32
    const float* r = g_rout + ((size_t)t * Bn + b) * Nn;
    float a0 = 0.f, a1 = 0.f, a2 = 0.f, a3 = 0.f;
    for (int n = 0; n < Nn; n += 4) {
        a0 = fmaf(r[n + 0], wout[(size_t)(n + 0) * NOn + oo], a0);
        a1 = fmaf(r[n + 1], wout[(size_t)(n + 1) * NOn + oo], a1);
        a2 = fmaf(r[n + 2], wout[(size_t)(n + 2) * NOn + oo], a2);
        a3 = fmaf(r[n + 3], wout[(size_t)(n + 3) * NOn + oo], a3);
    }
    g_h2[((size_t)b * Tn + t) * NOn + oo] = (a0 + a1) + (a2 + a3);
}

// ---------------- readout: leaky scan over t ---------------------------------
__global__ void k_scan(float* __restrict__ out) {
    int tid = threadIdx.x;               // 256 = B*NO
    int b = tid >> 5, oo = tid & 31;
    float o = 0.f;
    for (int t = 0; t < Tn; t++) {
        o = 0.9f * o + g_h2[((size_t)b * Tn + t) * NOn + oo];
        out[((size_t)b * Tn + t) * NOn + oo] = o;
    }
}

// ---------------- launch -----------------------------------------------------
extern "C" void kernel_launch(void* const* d_in, const int* in_sizes, int n_in,
                              void* d_out, int out_size) {
    const float* inputs  = (const float*)d_in[0];
    const float* w       = (const float*)d_in[1];
    const float* w_in    = (const float*)d_in[2];
    const float* w_out   = (const float*)d_in[3];
    const float* dmap    = (const float*)d_in[4];
    const int*   delays  = (const int*)d_in[5];
    const float* w_signs = (const float*)d_in[6];
    const float* p       = (const float*)d_in[7];
    const float* A_p     = (const float*)d_in[8];
    const float* A_d     = (const float*)d_in[9];
    float* out = (float*)d_out;

    const int smem_bytes = OB * Nn * 4 + Dn * Nn * 16 + 2048;   // ~100 KB
    cudaFuncSetAttribute(k_step, cudaFuncAttributeMaxDynamicSharedMemorySize,
                         smem_bytes);

    k_pack<<<256, 256>>>(w, w_signs, A_p, A_d, dmap);
    k_inp<<<64, 256>>>(inputs, w_in);
    k_step<<<NBLK, NTHR, smem_bytes>>>(delays, p);
    k_h2<<<Bn * Tn, NOn>>>(w_out);
    k_scan<<<1, Bn * NOn>>>(out);
}